// round 8
// baseline (speedup 1.0000x reference)
#include <cuda_runtime.h>
#include <cstdint>

// Problem constants
#define B_  32
#define C_  128
#define H_  36
#define W_  100
#define KW  9

#define WSKEW 4   // extra floats per 16-ci block in weight smem (bank de-conflict)
#define PSKEW 4   // extra floats per 16-ci block in prev-row smem

// Scratch ping-pong buffers (device globals: no runtime allocation allowed)
__device__ float g_buf0[(size_t)B_ * C_ * H_ * W_];
__device__ float g_buf1[(size_t)B_ * C_ * H_ * W_];

static __device__ __forceinline__ void cluster_sync() {
    asm volatile("barrier.cluster.arrive.aligned;" ::: "memory");
    asm volatile("barrier.cluster.wait.aligned;" ::: "memory");
}

#define FMA2(d, a, b, c) \
    asm("fma.rn.f32x2 %0, %1, %2, %3;" : "=l"(d) : "l"(a), "l"(b), "l"(c))
#define PACK2(d, v) \
    asm("mov.b64 %0, {%1, %1};" : "=l"(d) : "f"(v))
#define UNPACK2(lo, hi, p) \
    asm("mov.b64 {%0, %1}, %2;" : "=f"(lo), "=f"(hi) : "l"(p))

// One SCNN message-passing pass over a [B, C, S, L] tensor:
// scan over dim 2 (length S), 1D conv (K=9, pad 4) along contiguous dim 3.
// Cluster of 4 CTAs per batch; CTA g owns output channels [32g, 32g+32).
// Weights live in SMEM all pass; prev row re-read from pass output via L2.
// Each thread: 4 output channels (2 f32x2 pairs) x 4 consecutive w.
// All 9 k-step weight pairs are preloaded to registers so the 72-FMA2 block
// is stall-free; p loads are software-pipelined one ci ahead; next step's
// skip input is prefetched before the cluster barrier.
template <int S, int L, int CI_SPLIT, int BLOCK>
__global__ void __launch_bounds__(BLOCK, 1) __cluster_dims__(4, 1, 1)
scnn_pass(const float* __restrict__ in, const float* __restrict__ wts,
          float* __restrict__ out, int rev)
{
    constexpr int PS   = L + 8;          // padded row stride (4 zeros each side)
    constexpr int L4   = L / 4;
    constexpr int NWT  = L4;             // 4-wide w tiles
    constexpr int CHS  = S * L;
    constexpr int CIN  = C_ / CI_SPLIT;
    constexpr int WROW = KW * 32;        // floats per ci in weight smem (no skew)
    constexpr int WFL  = C_ * WROW + (C_ / 16) * WSKEW;
    constexpr int PPF  = C_ * PS + (C_ / 16) * PSKEW;
    constexpr int NX   = (32 * L4 + BLOCK - 1) / BLOCK;   // xsm staging iters

    extern __shared__ float smem[];
    float* wsm = smem;            // skewed [ci][k][co32]
    float* pp  = smem + WFL;      // skewed [ci][PS]
    float* xsm = pp + PPF;        // [32 co][L] staged skip-connection row

    const int tid = threadIdx.x;
    const int g   = blockIdx.x;
    const int b   = blockIdx.y;
    const int co0 = g * 32;

    const float* inB  = in  + (size_t)b * C_ * CHS;
    float*       outB = out + (size_t)b * C_ * CHS;

    uint32_t sbase;
    asm("{ .reg .u64 t; cvta.to.shared.u64 t, %1; cvt.u32.u64 %0, t; }"
        : "=r"(sbase) : "l"(smem));

    // ---- load weight slice w[co0..co0+31][ci][k] into skewed smem ----
    {
        const float* wg = wts + (size_t)co0 * (C_ * KW);
        for (int idx = tid; idx < 32 * C_ * KW; idx += BLOCK) {
            int col = idx / (C_ * KW);
            int r   = idx - col * (C_ * KW);      // ci*9 + k
            int ci  = r / KW;
            int k   = r - ci * KW;
            wsm[ci * WROW + (ci >> 4) * WSKEW + k * 32 + col] = wg[idx];
        }
    }
    for (int idx = tid; idx < PPF; idx += BLOCK) pp[idx] = 0.0f;

    // ---- thread -> (2 co-pairs = 4 co) x (4 consecutive w), ci split ----
    const int  task = tid / CI_SPLIT;
    const int  ciq  = tid % CI_SPLIT;
    const int  wt   = task % NWT;
    const int  cot  = task / NWT;
    const bool act  = (cot < 8);
    const int  w0   = wt * 4;
    const int  colB = (cot & 7) * 4;
    const int  ci0  = ciq * CIN;
    const bool wb   = act && (ciq == 0);       // writer thread for this tile

    const uint32_t wadr0 = sbase +
        (uint32_t)(ci0 * WROW + (ci0 >> 4) * WSKEW + colB) * 4u;
    const float* prow0 = pp + ci0 * PS + (ci0 >> 4) * PSKEW + w0;

    __syncthreads();

    for (int step = 0; step < S; ++step) {
        const int    p      = rev ? (S - 1 - step) : step;
        const size_t rowOff = (size_t)p * L;
        const int    pn     = rev ? (p - 1) : (p + 1);   // next step's row

        if (step == 0) {
            for (int idx = tid; idx < 32 * L4; idx += BLOCK) {
                int c = idx / L4, j = idx - c * L4;
                const size_t o = (size_t)(co0 + c) * CHS + rowOff + 4 * j;
                *reinterpret_cast<float4*>(outB + o) =
                    *reinterpret_cast<const float4*>(inB + o);
            }
            for (int idx = tid; idx < C_ * L4; idx += BLOCK) {
                int c = idx / L4, j = idx - c * L4;
                const float4 v = *reinterpret_cast<const float4*>(
                    inB + (size_t)c * CHS + rowOff + 4 * j);
                *reinterpret_cast<float4*>(
                    &pp[c * PS + (c >> 4) * PSKEW + 4 + 4 * j]) = v;
            }
            // stage next row's skip-connection input (own co slice)
            #pragma unroll
            for (int it = 0; it < NX; ++it) {
                int idx = tid + it * BLOCK;
                if (idx < 32 * L4) {
                    int c = idx / L4, j = idx - c * L4;
                    *reinterpret_cast<float4*>(&xsm[c * L + 4 * j]) =
                        *reinterpret_cast<const float4*>(
                            inB + (size_t)(co0 + c) * CHS + (size_t)pn * L + 4 * j);
                }
            }
            __syncthreads();
        } else {
            // acc2[pair][j]: pair 0 = co (colB,colB+1), pair 1 = (colB+2,colB+3)
            unsigned long long acc2[2][4] = {{0ull,0ull,0ull,0ull},
                                             {0ull,0ull,0ull,0ull}};
            if (act) {
                const float* prow = prow0;
                uint32_t     wadr = wadr0;
                // prime the p pipeline
                float4 va = *reinterpret_cast<const float4*>(prow);
                float4 vb = *reinterpret_cast<const float4*>(prow + 4);
                float4 vc = *reinterpret_cast<const float4*>(prow + 8);
                #pragma unroll 1
                for (int ci = 0; ci < CIN; ++ci) {
                    // preload ALL 9 weight pairs for this ci (36 regs) so the
                    // FMA2 block below has no in-loop LDS dependencies
                    unsigned long long w01[KW], w23[KW];
                    #pragma unroll
                    for (int k = 0; k < KW; ++k)
                        asm("ld.shared.v2.b64 {%0, %1}, [%2];"
                            : "=l"(w01[k]), "=l"(w23[k])
                            : "r"(wadr + (uint32_t)(k * 128)));

                    unsigned long long vp[12];
                    PACK2(vp[0],  va.x); PACK2(vp[1],  va.y);
                    PACK2(vp[2],  va.z); PACK2(vp[3],  va.w);
                    PACK2(vp[4],  vb.x); PACK2(vp[5],  vb.y);
                    PACK2(vp[6],  vb.z); PACK2(vp[7],  vb.w);
                    PACK2(vp[8],  vc.x); PACK2(vp[9],  vc.y);
                    PACK2(vp[10], vc.z); PACK2(vp[11], vc.w);

                    // advance p pointer; prefetch next ci's p during FMAs
                    prow += PS;
                    if (((ci0 + ci) & 15) == 15) prow += PSKEW;
                    if (ci + 1 < CIN) {
                        va = *reinterpret_cast<const float4*>(prow);
                        vb = *reinterpret_cast<const float4*>(prow + 4);
                        vc = *reinterpret_cast<const float4*>(prow + 8);
                    }

                    #pragma unroll
                    for (int k = 0; k < KW; ++k) {
                        #pragma unroll
                        for (int j = 0; j < 4; ++j) {
                            FMA2(acc2[0][j], w01[k], vp[j + k], acc2[0][j]);
                            FMA2(acc2[1][j], w23[k], vp[j + k], acc2[1][j]);
                        }
                    }
                    wadr += WROW * 4;
                    if (((ci0 + ci) & 15) == 15) wadr += WSKEW * 4;
                }
            }

            // unpack packed accumulators -> accf[a = co offset][j]
            float accf[4][4];
            #pragma unroll
            for (int pr = 0; pr < 2; ++pr)
                #pragma unroll
                for (int j = 0; j < 4; ++j)
                    UNPACK2(accf[2 * pr][j], accf[2 * pr + 1][j], acc2[pr][j]);

            if (CI_SPLIT > 1) {                      // reduce across ciq lanes
                #pragma unroll
                for (int a = 0; a < 4; ++a)
                    #pragma unroll
                    for (int j = 0; j < 4; ++j) {
                        float s = accf[a][j];
                        #pragma unroll
                        for (int off = CI_SPLIT >> 1; off > 0; off >>= 1)
                            s += __shfl_down_sync(0xffffffffu, s, off);
                        accf[a][j] = s;
                    }
            }

            if (wb) {
                #pragma unroll
                for (int a = 0; a < 4; ++a) {
                    const float* xr = &xsm[(colB + a) * L + w0];
                    const size_t o  = (size_t)(co0 + colB + a) * CHS + rowOff + w0;
                    const float4 x0 = *reinterpret_cast<const float4*>(xr);
                    float4 r0;
                    r0.x = x0.x + fmaxf(accf[a][0], 0.0f);
                    r0.y = x0.y + fmaxf(accf[a][1], 0.0f);
                    r0.z = x0.z + fmaxf(accf[a][2], 0.0f);
                    r0.w = x0.w + fmaxf(accf[a][3], 0.0f);
                    *reinterpret_cast<float4*>(outB + o) = r0;
                }
            }

            // prefetch next step's skip-connection row into registers BEFORE
            // the barrier (reads `in` only -> independent of peer CTAs)
            float4 xn[NX];
            if (step + 1 < S) {
                #pragma unroll
                for (int it = 0; it < NX; ++it) {
                    int idx = tid + it * BLOCK;
                    if (idx < 32 * L4) {
                        int c = idx / L4, j = idx - c * L4;
                        xn[it] = *reinterpret_cast<const float4*>(
                            inB + (size_t)(co0 + c) * CHS + (size_t)pn * L + 4 * j);
                    }
                }
            }

            cluster_sync();   // release our slice, wait for peers

            // reload full previous row (just-written out row p) via L2
            #pragma unroll
            for (int idx = tid; idx < C_ * L4; idx += BLOCK) {
                int c = idx / L4, j = idx - c * L4;
                const float4 v = __ldcg(reinterpret_cast<const float4*>(
                    outB + (size_t)c * CHS + rowOff + 4 * j));
                *reinterpret_cast<float4*>(
                    &pp[c * PS + (c >> 4) * PSKEW + 4 + 4 * j]) = v;
            }
            // commit the prefetched skip-connection row
            if (step + 1 < S) {
                #pragma unroll
                for (int it = 0; it < NX; ++it) {
                    int idx = tid + it * BLOCK;
                    if (idx < 32 * L4) {
                        int c = idx / L4, j = idx - c * L4;
                        *reinterpret_cast<float4*>(&xsm[c * L + 4 * j]) = xn[it];
                    }
                }
            }
            __syncthreads();
        }
    }
}

// [planes][Y][X] -> [planes][X][Y]
__global__ void transpose_k(const float* __restrict__ in, float* __restrict__ out,
                            int Y, int X)
{
    __shared__ float t[32][33];
    const size_t plane = (size_t)blockIdx.z * Y * X;
    const float* ip = in + plane;
    float*       op = out + plane;
    const int x0 = blockIdx.x * 32, y0 = blockIdx.y * 32;
    #pragma unroll
    for (int dy = threadIdx.y; dy < 32; dy += 8) {
        const int x = x0 + threadIdx.x, y = y0 + dy;
        if (x < X && y < Y) t[dy][threadIdx.x] = ip[(size_t)y * X + x];
    }
    __syncthreads();
    #pragma unroll
    for (int dy = threadIdx.y; dy < 32; dy += 8) {
        const int xo = y0 + threadIdx.x, yo = x0 + dy;
        if (xo < Y && yo < X) op[(size_t)yo * Y + xo] = t[threadIdx.x][dy];
    }
}

extern "C" void kernel_launch(void* const* d_in, const int* in_sizes, int n_in,
                              void* d_out, int out_size)
{
    const float* x    = (const float*)d_in[0];
    const float* w_ud = (const float*)d_in[1];
    const float* w_du = (const float*)d_in[2];
    const float* w_lr = (const float*)d_in[3];
    const float* w_rl = (const float*)d_in[4];
    float* out = (float*)d_out;

    float *b0, *b1;
    cudaGetSymbolAddress((void**)&b0, g_buf0);
    cudaGetSymbolAddress((void**)&b1, g_buf1);

    constexpr int WFL  = C_ * KW * 32 + (C_ / 16) * WSKEW;     // weight floats
    constexpr int SM_V = (WFL + C_ * (W_ + 8) + (C_ / 16) * PSKEW + 32 * W_) * 4;
    constexpr int SM_H = (WFL + C_ * (H_ + 8) + (C_ / 16) * PSKEW + 32 * H_) * 4;

    // vertical: 25 w-tiles x 8 cot x 2-way ci split = 400 thr, high ILP
    //           (reg cap 163 -> full weight preload + pipelining fits)
    // horizontal: 9 w-tiles x 8 cot x 8-way ci split = 576 thr (18 warps)
    cudaFuncSetAttribute(scnn_pass<H_, W_, 2, 400>,
                         cudaFuncAttributeMaxDynamicSharedMemorySize, SM_V);
    cudaFuncSetAttribute(scnn_pass<W_, H_, 8, 576>,
                         cudaFuncAttributeMaxDynamicSharedMemorySize, SM_H);

    const dim3 grid(4, B_, 1);

    // pass 1: down  (scan H, conv along W), layout [B,C,H,W]
    scnn_pass<H_, W_, 2, 400><<<grid, 400, SM_V>>>(x,  w_ud, b0, 0);
    // pass 2: up
    scnn_pass<H_, W_, 2, 400><<<grid, 400, SM_V>>>(b0, w_du, b1, 1);
    // transpose HW -> WH so horizontal rows become contiguous
    transpose_k<<<dim3((W_ + 31) / 32, (H_ + 31) / 32, B_ * C_), dim3(32, 8)>>>(
        b1, b0, H_, W_);
    // pass 3: left->right (scan W, conv along H), layout [B,C,W,H]
    scnn_pass<W_, H_, 8, 576><<<grid, 576, SM_H>>>(b0, w_lr, b1, 0);
    // pass 4: right->left
    scnn_pass<W_, H_, 8, 576><<<grid, 576, SM_H>>>(b1, w_rl, b0, 1);
    // transpose back WH -> HW into the output buffer
    transpose_k<<<dim3((H_ + 31) / 32, (W_ + 31) / 32, B_ * C_), dim3(32, 8)>>>(
        b0, out, W_, H_);
}

// round 9
// speedup vs baseline: 1.1933x; 1.1933x over previous
#include <cuda_runtime.h>
#include <cstdint>

// Problem constants
#define B_  32
#define C_  128
#define H_  36
#define W_  100
#define KW  9

#define WSKEW 4   // extra floats per 16-ci block in weight smem (bank de-conflict)
#define PSKEW 4   // extra floats per 16-ci block in prev-row smem

// Scratch ping-pong buffers (device globals: no runtime allocation allowed)
__device__ float g_buf0[(size_t)B_ * C_ * H_ * W_];
__device__ float g_buf1[(size_t)B_ * C_ * H_ * W_];

static __device__ __forceinline__ void cluster_sync() {
    asm volatile("barrier.cluster.arrive.aligned;" ::: "memory");
    asm volatile("barrier.cluster.wait.aligned;" ::: "memory");
}

#define FMA2(d, a, b, c) \
    asm("fma.rn.f32x2 %0, %1, %2, %3;" : "=l"(d) : "l"(a), "l"(b), "l"(c))
#define PACK2(d, v) \
    asm("mov.b64 %0, {%1, %1};" : "=l"(d) : "f"(v))
#define UNPACK2(lo, hi, p) \
    asm("mov.b64 {%0, %1}, %2;" : "=f"(lo), "=f"(hi) : "l"(p))

// One SCNN message-passing pass over a [B, C, S, L] tensor:
// scan over dim 2 (length S), 1D conv (K=9, pad 4) along contiguous dim 3.
// Cluster of 4 CTAs per batch; CTA g owns output channels [32g, 32g+32).
// Weights live in SMEM all pass; peers' prev-row slices re-read from the pass
// output via L2 each step; OWN slice is stored to smem straight from the
// writer registers after the cluster barrier (no L2 round trip).
// Each thread: 4 output channels (2 f32x2 pairs) x 4 consecutive w.
// PIPE=true software-pipelines p loads and the pre-barrier xin prefetch.
template <int S, int L, int CI_SPLIT, int BLOCK, bool PIPE>
__global__ void __launch_bounds__(BLOCK, 1) __cluster_dims__(4, 1, 1)
scnn_pass(const float* __restrict__ in, const float* __restrict__ wts,
          float* __restrict__ out, int rev)
{
    constexpr int PS   = L + 8;          // padded row stride (4 zeros each side)
    constexpr int L4   = L / 4;
    constexpr int NWT  = L4;             // 4-wide w tiles
    constexpr int CHS  = S * L;
    constexpr int CIN  = C_ / CI_SPLIT;
    constexpr int WROW = KW * 32;        // floats per ci in weight smem (no skew)
    constexpr int WFL  = C_ * WROW + (C_ / 16) * WSKEW;
    constexpr int PPF  = C_ * PS + (C_ / 16) * PSKEW;

    extern __shared__ float smem[];
    float* wsm = smem;            // skewed [ci][k][co32]
    float* pp  = smem + WFL;      // skewed [ci][PS]
    float* xsm = pp + PPF;        // [32 co][L] staged skip-connection row

    const int tid = threadIdx.x;
    const int g   = blockIdx.x;
    const int b   = blockIdx.y;
    const int co0 = g * 32;

    const float* inB  = in  + (size_t)b * C_ * CHS;
    float*       outB = out + (size_t)b * C_ * CHS;

    uint32_t sbase;
    asm("{ .reg .u64 t; cvta.to.shared.u64 t, %1; cvt.u32.u64 %0, t; }"
        : "=r"(sbase) : "l"(smem));

    // ---- load weight slice w[co0..co0+31][ci][k] into skewed smem ----
    {
        const float* wg = wts + (size_t)co0 * (C_ * KW);
        for (int idx = tid; idx < 32 * C_ * KW; idx += BLOCK) {
            int col = idx / (C_ * KW);
            int r   = idx - col * (C_ * KW);      // ci*9 + k
            int ci  = r / KW;
            int k   = r - ci * KW;
            wsm[ci * WROW + (ci >> 4) * WSKEW + k * 32 + col] = wg[idx];
        }
    }
    for (int idx = tid; idx < PPF; idx += BLOCK) pp[idx] = 0.0f;

    // ---- thread -> (2 co-pairs = 4 co) x (4 consecutive w), ci split ----
    const int  task = tid / CI_SPLIT;
    const int  ciq  = tid % CI_SPLIT;
    const int  wt   = task % NWT;
    const int  cot  = task / NWT;
    const bool act  = (cot < 8);
    const int  w0   = wt * 4;
    const int  colB = (cot & 7) * 4;
    const int  ci0  = ciq * CIN;
    const bool wb   = act && (ciq == 0);       // writer thread for this tile

    const uint32_t wadr0 = sbase +
        (uint32_t)(ci0 * WROW + (ci0 >> 4) * WSKEW + colB) * 4u;
    const float* prow0 = pp + ci0 * PS + (ci0 >> 4) * PSKEW + w0;

    // staging task for xsm (one float4 per thread; 32*L4 <= BLOCK always)
    const int  sc   = tid / L4;                 // co (0..31) for staging
    const int  sj   = tid - sc * L4;            // float4 index in row
    const bool sact = (tid < 32 * L4);

    __syncthreads();

    for (int step = 0; step < S; ++step) {
        const int    p      = rev ? (S - 1 - step) : step;
        const size_t rowOff = (size_t)p * L;
        const int    pn     = rev ? (p - 1) : (p + 1);   // next step's row

        if (step == 0) {
            for (int idx = tid; idx < 32 * L4; idx += BLOCK) {
                int c = idx / L4, j = idx - c * L4;
                const size_t o = (size_t)(co0 + c) * CHS + rowOff + 4 * j;
                *reinterpret_cast<float4*>(outB + o) =
                    *reinterpret_cast<const float4*>(inB + o);
            }
            for (int idx = tid; idx < C_ * L4; idx += BLOCK) {
                int c = idx / L4, j = idx - c * L4;
                const float4 v = *reinterpret_cast<const float4*>(
                    inB + (size_t)c * CHS + rowOff + 4 * j);
                *reinterpret_cast<float4*>(
                    &pp[c * PS + (c >> 4) * PSKEW + 4 + 4 * j]) = v;
            }
            // stage next row's skip-connection input (own co slice)
            if (sact)
                *reinterpret_cast<float4*>(&xsm[sc * L + 4 * sj]) =
                    *reinterpret_cast<const float4*>(
                        inB + (size_t)(co0 + sc) * CHS + (size_t)pn * L + 4 * sj);
            __syncthreads();
        } else {
            // acc2[pair][j]: pair 0 = co (colB,colB+1), pair 1 = (colB+2,colB+3)
            unsigned long long acc2[2][4] = {{0ull,0ull,0ull,0ull},
                                             {0ull,0ull,0ull,0ull}};
            if (act) {
                const float* prow = prow0;
                uint32_t     wadr = wadr0;
                float4 va, vb, vc;
                if (PIPE) {          // prime the pipeline
                    va = *reinterpret_cast<const float4*>(prow);
                    vb = *reinterpret_cast<const float4*>(prow + 4);
                    vc = *reinterpret_cast<const float4*>(prow + 8);
                }
                #pragma unroll 2
                for (int ci = 0; ci < CIN; ++ci) {
                    if (!PIPE) {
                        va = *reinterpret_cast<const float4*>(prow);
                        vb = *reinterpret_cast<const float4*>(prow + 4);
                        vc = *reinterpret_cast<const float4*>(prow + 8);
                    }
                    unsigned long long vp[12];
                    PACK2(vp[0],  va.x); PACK2(vp[1],  va.y);
                    PACK2(vp[2],  va.z); PACK2(vp[3],  va.w);
                    PACK2(vp[4],  vb.x); PACK2(vp[5],  vb.y);
                    PACK2(vp[6],  vb.z); PACK2(vp[7],  vb.w);
                    PACK2(vp[8],  vc.x); PACK2(vp[9],  vc.y);
                    PACK2(vp[10], vc.z); PACK2(vp[11], vc.w);

                    // advance p pointer; prefetch next ci's p during FMAs
                    prow += PS;
                    if (((ci0 + ci) & 15) == 15) prow += PSKEW;
                    if (PIPE && ci + 1 < CIN) {
                        va = *reinterpret_cast<const float4*>(prow);
                        vb = *reinterpret_cast<const float4*>(prow + 4);
                        vc = *reinterpret_cast<const float4*>(prow + 8);
                    }

                    #pragma unroll
                    for (int k = 0; k < KW; ++k) {
                        unsigned long long w01, w23;
                        asm("ld.shared.v2.b64 {%0, %1}, [%2];"
                            : "=l"(w01), "=l"(w23)
                            : "r"(wadr + (uint32_t)(k * 128)));
                        #pragma unroll
                        for (int j = 0; j < 4; ++j) {
                            FMA2(acc2[0][j], w01, vp[j + k], acc2[0][j]);
                            FMA2(acc2[1][j], w23, vp[j + k], acc2[1][j]);
                        }
                    }
                    wadr += WROW * 4;
                    if (((ci0 + ci) & 15) == 15) wadr += WSKEW * 4;
                }
            }

            // unpack packed accumulators -> accf[a = co offset][j]
            float accf[4][4];
            #pragma unroll
            for (int pr = 0; pr < 2; ++pr)
                #pragma unroll
                for (int j = 0; j < 4; ++j)
                    UNPACK2(accf[2 * pr][j], accf[2 * pr + 1][j], acc2[pr][j]);

            if (CI_SPLIT > 1) {                      // reduce across ciq lanes
                #pragma unroll
                for (int a = 0; a < 4; ++a)
                    #pragma unroll
                    for (int j = 0; j < 4; ++j) {
                        float s = accf[a][j];
                        #pragma unroll
                        for (int off = CI_SPLIT >> 1; off > 0; off >>= 1)
                            s += __shfl_down_sync(0xffffffffu, s, off);
                        accf[a][j] = s;
                    }
            }

            // finalize own rows: r = x + relu(conv); store to gmem (peers
            // will read it) and KEEP in registers for the post-barrier STS
            float4 rr[4];
            if (wb) {
                #pragma unroll
                for (int a = 0; a < 4; ++a) {
                    const float* xr = &xsm[(colB + a) * L + w0];
                    const size_t o  = (size_t)(co0 + colB + a) * CHS + rowOff + w0;
                    const float4 x0 = *reinterpret_cast<const float4*>(xr);
                    rr[a].x = x0.x + fmaxf(accf[a][0], 0.0f);
                    rr[a].y = x0.y + fmaxf(accf[a][1], 0.0f);
                    rr[a].z = x0.z + fmaxf(accf[a][2], 0.0f);
                    rr[a].w = x0.w + fmaxf(accf[a][3], 0.0f);
                    *reinterpret_cast<float4*>(outB + o) = rr[a];
                }
            }

            // prefetch next step's skip-connection row into registers BEFORE
            // the barrier (reads `in` only -> independent of peer CTAs)
            float4 xn;
            const bool xnv = PIPE && sact && (step + 1 < S);
            if (xnv)
                xn = *reinterpret_cast<const float4*>(
                    inB + (size_t)(co0 + sc) * CHS + (size_t)pn * L + 4 * sj);

            cluster_sync();   // release our slice, wait for peers

            // own 32 channels: store straight from registers (no L2 trip)
            if (wb) {
                #pragma unroll
                for (int a = 0; a < 4; ++a) {
                    const int c = co0 + colB + a;
                    *reinterpret_cast<float4*>(
                        &pp[c * PS + (c >> 4) * PSKEW + 4 + w0]) = rr[a];
                }
            }
            // peers' 96 channels: reload just-written out row p via L2
            for (int idx = tid; idx < 96 * L4; idx += BLOCK) {
                int ch = idx / L4, j = idx - ch * L4;
                int c  = (co0 + 32 + ch) & (C_ - 1);
                const float4 v = __ldcg(reinterpret_cast<const float4*>(
                    outB + (size_t)c * CHS + rowOff + 4 * j));
                *reinterpret_cast<float4*>(
                    &pp[c * PS + (c >> 4) * PSKEW + 4 + 4 * j]) = v;
            }
            // stage next step's skip-connection row (own co slice)
            if (PIPE) {
                if (xnv)
                    *reinterpret_cast<float4*>(&xsm[sc * L + 4 * sj]) = xn;
            } else if (sact && (step + 1 < S)) {
                *reinterpret_cast<float4*>(&xsm[sc * L + 4 * sj]) =
                    *reinterpret_cast<const float4*>(
                        inB + (size_t)(co0 + sc) * CHS + (size_t)pn * L + 4 * sj);
            }
            __syncthreads();
        }
    }
}

// [planes][Y][X] -> [planes][X][Y]
__global__ void transpose_k(const float* __restrict__ in, float* __restrict__ out,
                            int Y, int X)
{
    __shared__ float t[32][33];
    const size_t plane = (size_t)blockIdx.z * Y * X;
    const float* ip = in + plane;
    float*       op = out + plane;
    const int x0 = blockIdx.x * 32, y0 = blockIdx.y * 32;
    #pragma unroll
    for (int dy = threadIdx.y; dy < 32; dy += 8) {
        const int x = x0 + threadIdx.x, y = y0 + dy;
        if (x < X && y < Y) t[dy][threadIdx.x] = ip[(size_t)y * X + x];
    }
    __syncthreads();
    #pragma unroll
    for (int dy = threadIdx.y; dy < 32; dy += 8) {
        const int xo = y0 + threadIdx.x, yo = x0 + dy;
        if (xo < Y && yo < X) op[(size_t)yo * Y + xo] = t[threadIdx.x][dy];
    }
}

extern "C" void kernel_launch(void* const* d_in, const int* in_sizes, int n_in,
                              void* d_out, int out_size)
{
    const float* x    = (const float*)d_in[0];
    const float* w_ud = (const float*)d_in[1];
    const float* w_du = (const float*)d_in[2];
    const float* w_lr = (const float*)d_in[3];
    const float* w_rl = (const float*)d_in[4];
    float* out = (float*)d_out;

    float *b0, *b1;
    cudaGetSymbolAddress((void**)&b0, g_buf0);
    cudaGetSymbolAddress((void**)&b1, g_buf1);

    constexpr int WFL  = C_ * KW * 32 + (C_ / 16) * WSKEW;     // weight floats
    constexpr int SM_V = (WFL + C_ * (W_ + 8) + (C_ / 16) * PSKEW + 32 * W_) * 4;
    constexpr int SM_H = (WFL + C_ * (H_ + 8) + (C_ / 16) * PSKEW + 32 * H_) * 4;

    // vertical: 25 w-tiles x 8 cot x 4-way ci split = 800 thr (25 warps),
    //           no pipelining (reg budget 80 at 800 thr)
    // horizontal: 9 w-tiles x 8 cot x 8-way ci split = 576 thr (18 warps),
    //           pipelined p loads + pre-barrier x prefetch
    cudaFuncSetAttribute(scnn_pass<H_, W_, 4, 800, false>,
                         cudaFuncAttributeMaxDynamicSharedMemorySize, SM_V);
    cudaFuncSetAttribute(scnn_pass<W_, H_, 8, 576, true>,
                         cudaFuncAttributeMaxDynamicSharedMemorySize, SM_H);

    const dim3 grid(4, B_, 1);

    // pass 1: down  (scan H, conv along W), layout [B,C,H,W]
    scnn_pass<H_, W_, 4, 800, false><<<grid, 800, SM_V>>>(x,  w_ud, b0, 0);
    // pass 2: up
    scnn_pass<H_, W_, 4, 800, false><<<grid, 800, SM_V>>>(b0, w_du, b1, 1);
    // transpose HW -> WH so horizontal rows become contiguous
    transpose_k<<<dim3((W_ + 31) / 32, (H_ + 31) / 32, B_ * C_), dim3(32, 8)>>>(
        b1, b0, H_, W_);
    // pass 3: left->right (scan W, conv along H), layout [B,C,W,H]
    scnn_pass<W_, H_, 8, 576, true><<<grid, 576, SM_H>>>(b0, w_lr, b1, 0);
    // pass 4: right->left
    scnn_pass<W_, H_, 8, 576, true><<<grid, 576, SM_H>>>(b1, w_rl, b0, 1);
    // transpose back WH -> HW into the output buffer
    transpose_k<<<dim3((H_ + 31) / 32, (W_ + 31) / 32, B_ * C_), dim3(32, 8)>>>(
        b0, out, W_, H_);
}